// round 3
// baseline (speedup 1.0000x reference)
#include <cuda_runtime.h>
#include <cuda_bf16.h>
#include <cstdint>

#define N_NODES_MAX 50000
#define DIM 128
#define NOUT 384
#define EPS_F 1e-6f

// ---------------- scratch (static device globals; no allocation) ----------------
__device__ __align__(16) __nv_bfloat16 g_Wall[NOUT * DIM];                  // [Wchi; Wphi@Wchi; Wvarphi]
__device__ __align__(16) __nv_bfloat16 g_Tab[(size_t)N_NODES_MAX * NOUT];   // per node: x[128]|z[128]|v[128]
__device__ __align__(16) float g_acc[(size_t)N_NODES_MAX * DIM];            // scatter accumulator
__device__ float g_degree[N_NODES_MAX];
__device__ float g_normsq[N_NODES_MAX];
__device__ float g_coef[N_NODES_MAX];

// ---------------- W prep: rows 0-127 = Wchi, 128-255 = Wphi@Wchi, 256-383 = Wvarphi
__global__ void prep_w_kernel(const float* __restrict__ Wchi,
                              const float* __restrict__ Wphi,
                              const float* __restrict__ Wvphi) {
    int i = blockIdx.x;   // 0..127
    int j = threadIdx.x;  // 0..127
    float s = 0.f;
#pragma unroll 8
    for (int k = 0; k < DIM; k++) s += Wphi[i * DIM + k] * Wchi[k * DIM + j];
    g_Wall[i * DIM + j]         = __float2bfloat16(Wchi[i * DIM + j]);
    g_Wall[(128 + i) * DIM + j] = __float2bfloat16(s);
    g_Wall[(256 + i) * DIM + j] = __float2bfloat16(Wvphi[i * DIM + j]);
}

// ---------------- x -> bf16 into table x-slot
__global__ void conv_x_kernel(const float* __restrict__ x, int nNodes) {
    int i = blockIdx.x * blockDim.x + threadIdx.x;   // over nNodes*64 bf16x2 units
    if (i < nNodes * 64) {
        int node = i >> 6, kp = i & 63;
        float2 v = reinterpret_cast<const float2*>(x)[i];
        reinterpret_cast<__nv_bfloat162*>(g_Tab)[(size_t)node * 192 + kp] =
            __float22bfloat162_rn(v);
    }
}

// ---------------- degree (segment sum of edge_weight by row)  [edge_index is int32]
__global__ void degree_kernel(const int* __restrict__ ei,
                              const float* __restrict__ ew, int E) {
    int e = blockIdx.x * blockDim.x + threadIdx.x;
    if (e < E) atomicAdd(&g_degree[ei[e]], ew[e]);
}

// ---------------- fused node GEMM: X(bf16) @ Wall^T -> normsq(y), z, v into table
// CTA: 64 nodes x 384 outputs, K=128 in smem. 8 warps: 4(M) x 2(N=192 each).
__global__ __launch_bounds__(256, 1) void gemm_kernel(int nNodes) {
    extern __shared__ unsigned smem_u[];
    unsigned* Bs = smem_u;                 // [384][68] padded
    unsigned* As = smem_u + NOUT * 68;     // [64][68]

    int tid = threadIdx.x;
    const unsigned* Wsrc = reinterpret_cast<const unsigned*>(g_Wall);
    for (int idx = tid; idx < NOUT * 64; idx += 256) {
        int n = idx >> 6, kp = idx & 63;
        Bs[n * 68 + kp] = Wsrc[idx];
    }
    int base = blockIdx.x * 64;
    const unsigned* Tsrc = reinterpret_cast<const unsigned*>(g_Tab);
    for (int idx = tid; idx < 64 * 64; idx += 256) {
        int r = idx >> 6, kp = idx & 63;
        int node = base + r;
        As[r * 68 + kp] = (node < nNodes) ? Tsrc[(size_t)node * 192 + kp] : 0u;
    }
    __syncthreads();

    int warp = tid >> 5, lane = tid & 31;
    int g = lane >> 2, tig = lane & 3;
    int wm = warp & 3, wn = warp >> 2;

    float acc[24][4];
#pragma unroll
    for (int nt = 0; nt < 24; nt++) {
        acc[nt][0] = 0.f; acc[nt][1] = 0.f; acc[nt][2] = 0.f; acc[nt][3] = 0.f;
    }

    const unsigned* Arow0 = As + (wm * 16 + g) * 68;
    const unsigned* Arow1 = Arow0 + 8 * 68;

#pragma unroll
    for (int ks = 0; ks < 8; ks++) {
        unsigned a0 = Arow0[ks * 8 + tig];
        unsigned a1 = Arow1[ks * 8 + tig];
        unsigned a2 = Arow0[ks * 8 + tig + 4];
        unsigned a3 = Arow1[ks * 8 + tig + 4];
#pragma unroll
        for (int nt = 0; nt < 24; nt++) {
            int n = wn * 192 + nt * 8 + g;
            unsigned b0 = Bs[n * 68 + ks * 8 + tig];
            unsigned b1 = Bs[n * 68 + ks * 8 + tig + 4];
            asm volatile(
                "mma.sync.aligned.m16n8k16.row.col.f32.bf16.bf16.f32 "
                "{%0,%1,%2,%3},{%4,%5,%6,%7},{%8,%9},{%0,%1,%2,%3};\n"
                : "+f"(acc[nt][0]), "+f"(acc[nt][1]), "+f"(acc[nt][2]), "+f"(acc[nt][3])
                : "r"(a0), "r"(a1), "r"(a2), "r"(a3), "r"(b0), "r"(b1));
        }
    }

    int node0 = base + wm * 16 + g;
    int node1 = node0 + 8;
#pragma unroll
    for (int nt = 0; nt < 24; nt++) {
        int jc = wn * 192 + nt * 8 + 2 * tig;   // output column (even)
        if (jc < 128) {  // y part: squared-norm accumulation
            if (node0 < nNodes)
                atomicAdd(&g_normsq[node0], acc[nt][0] * acc[nt][0] + acc[nt][1] * acc[nt][1]);
            if (node1 < nNodes)
                atomicAdd(&g_normsq[node1], acc[nt][2] * acc[nt][2] + acc[nt][3] * acc[nt][3]);
        } else {         // z/v part -> table columns 128..383
            if (node0 < nNodes) {
                __nv_bfloat162 h = __float22bfloat162_rn(make_float2(acc[nt][0], acc[nt][1]));
                *reinterpret_cast<unsigned*>(&g_Tab[(size_t)node0 * NOUT + jc]) =
                    *reinterpret_cast<unsigned*>(&h);
            }
            if (node1 < nNodes) {
                __nv_bfloat162 h = __float22bfloat162_rn(make_float2(acc[nt][2], acc[nt][3]));
                *reinterpret_cast<unsigned*>(&g_Tab[(size_t)node1 * NOUT + jc]) =
                    *reinterpret_cast<unsigned*>(&h);
            }
        }
    }
}

// ---------------- per-node coefficient: 1/(MU*degree*Phi_chi), 0 when degree==0
__global__ void coef_kernel(int nNodes) {
    int i = blockIdx.x * blockDim.x + threadIdx.x;
    if (i < nNodes) {
        float d = g_degree[i];
        g_coef[i] = (d > 0.f) ? 1.0f / (d * tanhf(sqrtf(g_normsq[i]))) : 0.f;
    }
}

// ---------------- edge kernel: one warp per edge, all operands bf16 from one table
__device__ __forceinline__ float2 bf2f(unsigned p) {
    return __bfloat1622float2(*reinterpret_cast<__nv_bfloat162*>(&p));
}

__global__ __launch_bounds__(256) void edge_kernel(const int* __restrict__ ei,
                                                   const float* __restrict__ ew, int E) {
    int e = (int)((blockIdx.x * 256u + threadIdx.x) >> 5);
    int lane = threadIdx.x & 31;
    if (e >= E) return;

    int row = ei[e];
    int col = ei[(size_t)E + e];
    float w = ew[e];

    const uint2* tr = reinterpret_cast<const uint2*>(g_Tab + (size_t)row * NOUT);
    const uint2* tc = reinterpret_cast<const uint2*>(g_Tab + (size_t)col * NOUT);
    uint2 xru = tr[lane],      xcu = tc[lane];        // x slots 0..31
    uint2 zru = tr[32 + lane], zcu = tc[32 + lane];   // z slots 32..63
    uint2 vru = tr[64 + lane], vcu = tc[64 + lane];   // v slots 64..95

    // diff (4 floats per lane) from bf16 x
    float2 xa0 = bf2f(xru.x), xa1 = bf2f(xru.y);
    float2 xb0 = bf2f(xcu.x), xb1 = bf2f(xcu.y);
    float d0 = xa0.x - xb0.x, d1 = xa0.y - xb0.y;
    float d2 = xa1.x - xb1.x, d3 = xa1.y - xb1.y;

    float2 za0 = bf2f(zru.x), za1 = bf2f(zru.y);
    float2 zb0 = bf2f(zcu.x), zb1 = bf2f(zcu.y);
    float dotz = za0.x * zb0.x + za0.y * zb0.y + za1.x * zb1.x + za1.y * zb1.y;

    float2 va0 = bf2f(vru.x), va1 = bf2f(vru.y);
    float2 vb0 = bf2f(vcu.x), vb1 = bf2f(vcu.y);
    float e0 = va0.x - vb0.x, e1 = va0.y - vb0.y;
    float e2 = va1.x - vb1.x, e3 = va1.y - vb1.y;
    float nv = e0 * e0 + e1 * e1 + e2 * e2 + e3 * e3;

#pragma unroll
    for (int o = 16; o; o >>= 1) {
        dotz += __shfl_xor_sync(0xffffffffu, dotz, o);
        nv   += __shfl_xor_sync(0xffffffffu, nv, o);
    }

    float s = w * tanhf(fabsf(dotz)) * tanhf(1.0f / (sqrtf(nv) + EPS_F));

    float* dst = g_acc + (size_t)row * DIM + lane * 4;
    float s0 = s * d0, s1 = s * d1, s2 = s * d2, s3 = s * d3;
    asm volatile("red.global.add.v4.f32 [%0], {%1,%2,%3,%4};"
                 :: "l"(dst), "f"(s0), "f"(s1), "f"(s2), "f"(s3) : "memory");
}

// ---------------- final: out = x - coef[n] * acc
__global__ void final_kernel(const float* __restrict__ x, float* __restrict__ out, int total4) {
    int i = blockIdx.x * blockDim.x + threadIdx.x;
    if (i < total4) {
        int node = i >> 5;  // 32 float4 per node
        float c = g_coef[node];
        float4 xv = reinterpret_cast<const float4*>(x)[i];
        float4 av = reinterpret_cast<const float4*>(g_acc)[i];
        reinterpret_cast<float4*>(out)[i] =
            make_float4(xv.x - c * av.x, xv.y - c * av.y, xv.z - c * av.z, xv.w - c * av.w);
    }
}

// ---------------- launch ----------------
extern "C" void kernel_launch(void* const* d_in, const int* in_sizes, int n_in,
                              void* d_out, int out_size) {
    const float* x     = (const float*)d_in[0];
    const int*   ei    = (const int*)d_in[1];     // JAX silently emits int32
    const float* ew    = (const float*)d_in[2];
    const float* Wchi  = (const float*)d_in[3];
    const float* Wphi  = (const float*)d_in[4];
    const float* Wvphi = (const float*)d_in[5];

    int nNodes = in_sizes[0] / DIM;
    if (nNodes > N_NODES_MAX) nNodes = N_NODES_MAX;
    int E      = in_sizes[2];

    void *pAcc, *pDeg, *pNs;
    cudaGetSymbolAddress(&pAcc, g_acc);
    cudaGetSymbolAddress(&pDeg, g_degree);
    cudaGetSymbolAddress(&pNs,  g_normsq);
    cudaMemsetAsync(pAcc, 0, (size_t)nNodes * DIM * sizeof(float), 0);
    cudaMemsetAsync(pDeg, 0, (size_t)nNodes * sizeof(float), 0);
    cudaMemsetAsync(pNs,  0, (size_t)nNodes * sizeof(float), 0);

    prep_w_kernel<<<DIM, DIM>>>(Wchi, Wphi, Wvphi);

    int nUnits = nNodes * 64;
    conv_x_kernel<<<(nUnits + 255) / 256, 256>>>(x, nNodes);

    degree_kernel<<<(E + 255) / 256, 256>>>(ei, ew, E);

    int smem = (NOUT * 68 + 64 * 68) * 4;
    cudaFuncSetAttribute(gemm_kernel, cudaFuncAttributeMaxDynamicSharedMemorySize, smem);
    gemm_kernel<<<(nNodes + 63) / 64, 256, smem>>>(nNodes);

    coef_kernel<<<(nNodes + 255) / 256, 256>>>(nNodes);

    edge_kernel<<<(E + 7) / 8, 256>>>(ei, ew, E);

    int total4 = nNodes * DIM / 4;
    final_kernel<<<(total4 + 255) / 256, 256>>>(x, (float*)d_out, total4);
}

// round 4
// speedup vs baseline: 1.0873x; 1.0873x over previous
#include <cuda_runtime.h>
#include <cuda_bf16.h>
#include <cstdint>

#define N_NODES_MAX 50000
#define DIM 128
#define NOUT 384
#define EPS_F 1e-6f

// ---------------- scratch (static device globals; no allocation) ----------------
__device__ __align__(16) __nv_bfloat16 g_Wall[NOUT * DIM];   // rows 0-127: Wchi, 128-255: M1=(WphiWchi)^T(WphiWchi), 256-383: M2=Wv^T Wv
__device__ __align__(16) float g_T[DIM * DIM];               // T = Wphi @ Wchi (f32 staging)
__device__ __align__(16) __nv_bfloat16 g_Tab[(size_t)N_NODES_MAX * NOUT];  // per node: x[128]|p[128]|q[128]
__device__ __align__(16) float g_acc[(size_t)N_NODES_MAX * DIM];
__device__ float g_degree[N_NODES_MAX];
__device__ float g_normsq[N_NODES_MAX];   // |Wchi x|^2
__device__ float g_ndot[N_NODES_MAX];     // x^T M2 x = |Wv x|^2
__device__ float g_coef[N_NODES_MAX];

// ---------------- prep1: T = Wphi @ Wchi ; Wall rows 0-127 = bf16(Wchi)
__global__ void prep1_kernel(const float* __restrict__ Wchi,
                             const float* __restrict__ Wphi) {
    int i = blockIdx.x, j = threadIdx.x;
    float s = 0.f;
#pragma unroll 8
    for (int k = 0; k < DIM; k++) s += Wphi[i * DIM + k] * Wchi[k * DIM + j];
    g_T[i * DIM + j] = s;
    g_Wall[i * DIM + j] = __float2bfloat16(Wchi[i * DIM + j]);
}

// ---------------- prep2: M1 = T^T T -> rows 128-255 ; M2 = Wv^T Wv -> rows 256-383
__global__ void prep2_kernel(const float* __restrict__ Wvphi) {
    int i = blockIdx.x, j = threadIdx.x;
    float s1 = 0.f, s2 = 0.f;
#pragma unroll 8
    for (int k = 0; k < DIM; k++) {
        s1 += g_T[k * DIM + i] * g_T[k * DIM + j];
        s2 += Wvphi[k * DIM + i] * Wvphi[k * DIM + j];
    }
    g_Wall[(128 + i) * DIM + j] = __float2bfloat16(s1);
    g_Wall[(256 + i) * DIM + j] = __float2bfloat16(s2);
}

// ---------------- x -> bf16 into table x-slot
__global__ void conv_x_kernel(const float* __restrict__ x, int nNodes) {
    int i = blockIdx.x * blockDim.x + threadIdx.x;  // bf16x2 units
    if (i < nNodes * 64) {
        int node = i >> 6, kp = i & 63;
        float2 v = reinterpret_cast<const float2*>(x)[i];
        reinterpret_cast<__nv_bfloat162*>(g_Tab)[(size_t)node * 192 + kp] =
            __float22bfloat162_rn(v);
    }
}

// ---------------- degree (segment sum of edge_weight by row)
__global__ void degree_kernel(const int* __restrict__ ei,
                              const float* __restrict__ ew, int E) {
    int e = blockIdx.x * blockDim.x + threadIdx.x;
    if (e < E) atomicAdd(&g_degree[ei[e]], ew[e]);
}

// ---------------- node GEMM, sliced: blockIdx.y = slice (0:y->normsq, 1:p, 2:q+ndot)
// CTA: 128 nodes x 128 outputs. 8 warps: 4(M:32 rows) x 2(N:64 cols).
__global__ __launch_bounds__(256, 2) void gemm2_kernel(int nNodes) {
    extern __shared__ unsigned smem_u[];
    unsigned* Bs = smem_u;               // [128][68]
    unsigned* As = smem_u + 128 * 68;    // [128][68]
    float* sm_red = (float*)(smem_u + 2 * 128 * 68);  // [128]

    int tid = threadIdx.x;
    int slice = blockIdx.y;
    int base = blockIdx.x * 128;

    if (tid < 128) sm_red[tid] = 0.f;

    const unsigned* Wsrc = reinterpret_cast<const unsigned*>(g_Wall) + slice * 128 * 64;
    for (int idx = tid; idx < 128 * 64; idx += 256) {
        int n = idx >> 6, kp = idx & 63;
        Bs[n * 68 + kp] = Wsrc[idx];
    }
    const unsigned* Tsrc = reinterpret_cast<const unsigned*>(g_Tab);
    for (int idx = tid; idx < 128 * 64; idx += 256) {
        int r = idx >> 6, kp = idx & 63;
        int node = base + r;
        As[r * 68 + kp] = (node < nNodes) ? Tsrc[(size_t)node * 192 + kp] : 0u;
    }
    __syncthreads();

    int warp = tid >> 5, lane = tid & 31;
    int g = lane >> 2, tig = lane & 3;
    int wm = warp & 3, wn = warp >> 2;

    float acc[2][8][4];
#pragma unroll
    for (int t = 0; t < 2; t++)
#pragma unroll
        for (int nt = 0; nt < 8; nt++)
#pragma unroll
            for (int c = 0; c < 4; c++) acc[t][nt][c] = 0.f;

#pragma unroll
    for (int ks = 0; ks < 8; ks++) {
        unsigned a[2][4];
#pragma unroll
        for (int t = 0; t < 2; t++) {
            const unsigned* Ar = As + (wm * 32 + t * 16 + g) * 68 + ks * 8;
            a[t][0] = Ar[tig];
            a[t][1] = Ar[8 * 68 + tig];
            a[t][2] = Ar[tig + 4];
            a[t][3] = Ar[8 * 68 + tig + 4];
        }
#pragma unroll
        for (int nt = 0; nt < 8; nt++) {
            const unsigned* Br = Bs + (wn * 64 + nt * 8 + g) * 68 + ks * 8;
            unsigned b0 = Br[tig], b1 = Br[tig + 4];
#pragma unroll
            for (int t = 0; t < 2; t++) {
                asm volatile(
                    "mma.sync.aligned.m16n8k16.row.col.f32.bf16.bf16.f32 "
                    "{%0,%1,%2,%3},{%4,%5,%6,%7},{%8,%9},{%0,%1,%2,%3};\n"
                    : "+f"(acc[t][nt][0]), "+f"(acc[t][nt][1]),
                      "+f"(acc[t][nt][2]), "+f"(acc[t][nt][3])
                    : "r"(a[t][0]), "r"(a[t][1]), "r"(a[t][2]), "r"(a[t][3]),
                      "r"(b0), "r"(b1));
            }
        }
    }

    if (slice == 1 || slice == 2) {
        int colBase = (slice == 1) ? 128 : 256;
#pragma unroll
        for (int t = 0; t < 2; t++) {
            int ra = wm * 32 + t * 16 + g;      // CTA-local row for c0,c1
            int rb = ra + 8;                    // for c2,c3
            int na = base + ra, nb = base + rb;
#pragma unroll
            for (int nt = 0; nt < 8; nt++) {
                int jc = wn * 64 + nt * 8 + 2 * tig;
                if (na < nNodes) {
                    __nv_bfloat162 h = __float22bfloat162_rn(
                        make_float2(acc[t][nt][0], acc[t][nt][1]));
                    *reinterpret_cast<unsigned*>(&g_Tab[(size_t)na * NOUT + colBase + jc]) =
                        *reinterpret_cast<unsigned*>(&h);
                }
                if (nb < nNodes) {
                    __nv_bfloat162 h = __float22bfloat162_rn(
                        make_float2(acc[t][nt][2], acc[t][nt][3]));
                    *reinterpret_cast<unsigned*>(&g_Tab[(size_t)nb * NOUT + colBase + jc]) =
                        *reinterpret_cast<unsigned*>(&h);
                }
            }
        }
    }

    if (slice == 0) {
        // normsq = sum_j y_j^2, reduce in shared
#pragma unroll
        for (int t = 0; t < 2; t++) {
            int ra = wm * 32 + t * 16 + g, rb = ra + 8;
            float sa = 0.f, sb = 0.f;
#pragma unroll
            for (int nt = 0; nt < 8; nt++) {
                sa += acc[t][nt][0] * acc[t][nt][0] + acc[t][nt][1] * acc[t][nt][1];
                sb += acc[t][nt][2] * acc[t][nt][2] + acc[t][nt][3] * acc[t][nt][3];
            }
            atomicAdd(&sm_red[ra], sa);
            atomicAdd(&sm_red[rb], sb);
        }
        __syncthreads();
        if (tid < 128 && base + tid < nNodes) g_normsq[base + tid] = sm_red[tid];
    } else if (slice == 2) {
        // ndot = sum_j x_j * q_j  (x from As smem)
#pragma unroll
        for (int t = 0; t < 2; t++) {
            int ra = wm * 32 + t * 16 + g, rb = ra + 8;
            float sa = 0.f, sb = 0.f;
#pragma unroll
            for (int nt = 0; nt < 8; nt++) {
                int jp = (wn * 64 + nt * 8 + 2 * tig) >> 1;  // bf16x2 unit index
                unsigned xa = As[ra * 68 + jp];
                unsigned xb = As[rb * 68 + jp];
                float2 fa = __bfloat1622float2(*reinterpret_cast<__nv_bfloat162*>(&xa));
                float2 fb = __bfloat1622float2(*reinterpret_cast<__nv_bfloat162*>(&xb));
                sa += fa.x * acc[t][nt][0] + fa.y * acc[t][nt][1];
                sb += fb.x * acc[t][nt][2] + fb.y * acc[t][nt][3];
            }
            atomicAdd(&sm_red[ra], sa);
            atomicAdd(&sm_red[rb], sb);
        }
        __syncthreads();
        if (tid < 128 && base + tid < nNodes) g_ndot[base + tid] = sm_red[tid];
    }
}

// ---------------- per-node coefficient: 1/(degree*Phi_chi), 0 when degree==0
__global__ void coef_kernel(int nNodes) {
    int i = blockIdx.x * blockDim.x + threadIdx.x;
    if (i < nNodes) {
        float d = g_degree[i];
        g_coef[i] = (d > 0.f) ? 1.0f / (d * tanhf(sqrtf(g_normsq[i]))) : 0.f;
    }
}

// ---------------- edge kernel: one warp per edge
__device__ __forceinline__ float2 bf2f(unsigned p) {
    return __bfloat1622float2(*reinterpret_cast<__nv_bfloat162*>(&p));
}

__global__ __launch_bounds__(256) void edge_kernel(const int* __restrict__ ei,
                                                   const float* __restrict__ ew, int E) {
    int e = (int)((blockIdx.x * 256u + threadIdx.x) >> 5);
    int lane = threadIdx.x & 31;
    if (e >= E) return;

    int row = ei[e];
    int col = ei[(size_t)E + e];
    float w = ew[e];
    float nr = g_ndot[row], nc = g_ndot[col];

    const uint2* tr = reinterpret_cast<const uint2*>(g_Tab + (size_t)row * NOUT);
    const uint2* tc = reinterpret_cast<const uint2*>(g_Tab + (size_t)col * NOUT);
    uint2 xru = tr[lane];         // x_row
    uint2 xcu = tc[lane];         // x_col
    uint2 pcu = tc[32 + lane];    // p_col = M1 x_col
    uint2 qcu = tc[64 + lane];    // q_col = M2 x_col

    float2 xa0 = bf2f(xru.x), xa1 = bf2f(xru.y);
    float2 xb0 = bf2f(xcu.x), xb1 = bf2f(xcu.y);
    float d0 = xa0.x - xb0.x, d1 = xa0.y - xb0.y;
    float d2 = xa1.x - xb1.x, d3 = xa1.y - xb1.y;

    float2 p0 = bf2f(pcu.x), p1 = bf2f(pcu.y);
    float dotz = xa0.x * p0.x + xa0.y * p0.y + xa1.x * p1.x + xa1.y * p1.y;

    float2 q0 = bf2f(qcu.x), q1 = bf2f(qcu.y);
    float dq = xa0.x * q0.x + xa0.y * q0.y + xa1.x * q1.x + xa1.y * q1.y;

#pragma unroll
    for (int o = 16; o; o >>= 1) {
        dotz += __shfl_xor_sync(0xffffffffu, dotz, o);
        dq   += __shfl_xor_sync(0xffffffffu, dq, o);
    }

    float nv = fmaxf(nr + nc - 2.0f * dq, 0.0f);
    float s = w * tanhf(fabsf(dotz)) * tanhf(1.0f / (sqrtf(nv) + EPS_F));

    float* dst = g_acc + (size_t)row * DIM + lane * 4;
    float s0 = s * d0, s1 = s * d1, s2 = s * d2, s3 = s * d3;
    asm volatile("red.global.add.v4.f32 [%0], {%1,%2,%3,%4};"
                 :: "l"(dst), "f"(s0), "f"(s1), "f"(s2), "f"(s3) : "memory");
}

// ---------------- final: out = x - coef[n] * acc
__global__ void final_kernel(const float* __restrict__ x, float* __restrict__ out, int total4) {
    int i = blockIdx.x * blockDim.x + threadIdx.x;
    if (i < total4) {
        int node = i >> 5;
        float c = g_coef[node];
        float4 xv = reinterpret_cast<const float4*>(x)[i];
        float4 av = reinterpret_cast<const float4*>(g_acc)[i];
        reinterpret_cast<float4*>(out)[i] =
            make_float4(xv.x - c * av.x, xv.y - c * av.y, xv.z - c * av.z, xv.w - c * av.w);
    }
}

// ---------------- launch ----------------
extern "C" void kernel_launch(void* const* d_in, const int* in_sizes, int n_in,
                              void* d_out, int out_size) {
    const float* x     = (const float*)d_in[0];
    const int*   ei    = (const int*)d_in[1];   // JAX emits int32
    const float* ew    = (const float*)d_in[2];
    const float* Wchi  = (const float*)d_in[3];
    const float* Wphi  = (const float*)d_in[4];
    const float* Wvphi = (const float*)d_in[5];

    int nNodes = in_sizes[0] / DIM;
    if (nNodes > N_NODES_MAX) nNodes = N_NODES_MAX;
    int E = in_sizes[2];

    void *pAcc, *pDeg;
    cudaGetSymbolAddress(&pAcc, g_acc);
    cudaGetSymbolAddress(&pDeg, g_degree);
    cudaMemsetAsync(pAcc, 0, (size_t)nNodes * DIM * sizeof(float), 0);
    cudaMemsetAsync(pDeg, 0, (size_t)nNodes * sizeof(float), 0);

    prep1_kernel<<<DIM, DIM>>>(Wchi, Wphi);
    prep2_kernel<<<DIM, DIM>>>(Wvphi);

    int nUnits = nNodes * 64;
    conv_x_kernel<<<(nUnits + 255) / 256, 256>>>(x, nNodes);

    degree_kernel<<<(E + 255) / 256, 256>>>(ei, ew, E);

    int smem = (2 * 128 * 68 + 128) * 4;
    cudaFuncSetAttribute(gemm2_kernel, cudaFuncAttributeMaxDynamicSharedMemorySize, smem);
    dim3 ggrid((nNodes + 127) / 128, 3);
    gemm2_kernel<<<ggrid, 256, smem>>>(nNodes);

    coef_kernel<<<(nNodes + 255) / 256, 256>>>(nNodes);

    edge_kernel<<<(E + 7) / 8, 256>>>(ei, ew, E);

    int total4 = nNodes * DIM / 4;
    final_kernel<<<(total4 + 255) / 256, 256>>>(x, (float*)d_out, total4);
}